// round 8
// baseline (speedup 1.0000x reference)
#include <cuda_runtime.h>
#include <math.h>

// Problem dims (fixed)
#define Bsz   128
#define Tlen  512
#define Isz   256
#define Hsz   512
#define Osz   256

// Pod decomposition: 16 independent pods x 8 blocks; each pod owns 8 batches,
// each block owns 64 h-rows of W_hh (128KB fp32 in smem).
#define PODS  16
#define PODB  8      // blocks per pod
#define PB    8      // batches per pod
#define NBT   8      // xp batch tiles (of 16)

// Packed f32x2 helpers (ptxas never emits FFMA2 from C++; inline PTX required)
#define FMA2(acc, a, b) \
    asm("fma.rn.f32x2 %0, %1, %2, %0;" : "+l"(acc) : "l"(a), "l"(b))
#define ADD2(d, a, b) \
    asm("add.rn.f32x2 %0, %1, %2;" : "=l"(d) : "l"(a), "l"(b))
#define PACK2(d, lo, hi) \
    asm("mov.b64 %0, {%1, %2};" : "=l"(d) : "f"(lo), "f"(hi))
#define UNPACK2(lo, hi, v) \
    asm("mov.b64 {%0, %1}, %2;" : "=f"(lo), "=f"(hi) : "l"(v))

typedef unsigned long long u64;

// Scratch (device globals; no runtime allocation)
__device__ float    g_xp[(size_t)Tlen * PODS * Hsz * PB]; // [t][pod][h][8]
__device__ float    g_h[2][PODS * Hsz * PB];              // [parity][pod][k][8]
__device__ unsigned g_pbar_count[PODS * 32];              // 128B-padded per pod
__device__ unsigned g_pbar_gen[PODS * 32];

// ---------------------------------------------------------------------------
// x_proj: xp[t][pod][h][b] = sum_i inputs[b][t][i]*W_ih[h][i] + b_ih[h]+b_hh[h]
// grid (Tlen/TQ, NBT, Hsz/32), 256 threads. FFMA2, I-split 4.
// ---------------------------------------------------------------------------
#define TQ  8
#define XSROW 257

__global__ void __launch_bounds__(256) xp_kernel(
    const float* __restrict__ inputs, const float* __restrict__ W_ih,
    const float* __restrict__ b_ih,   const float* __restrict__ b_hh)
{
    extern __shared__ float smem[];
    float* Wt  = smem;                              // [256][32]: Wt[i][j]=W_ih[h0+j][i]
    u64*   xs2 = (u64*)(smem + 8192);               // [16][257]: xs2[b][i]={x,x}
    u64*   red = (u64*)(smem + 8192 + 2 * 16 * XSROW);  // [4][16][16]
    const u64* Wtu = (const u64*)Wt;

    const int tq = blockIdx.x, bt = blockIdx.y, ht = blockIdx.z;
    const int h0 = ht * 32, b0 = bt * 16;
    const int tid = threadIdx.x;

    // Stage W_ih tile transposed (once)
    {
        const int lane_j = tid & 31, qb = tid >> 5;          // qb 0..7
        for (int r = 0; r < 8; r++) {
            int q = qb + 8 * r;                              // 0..63
            float4 w = *(const float4*)&W_ih[(h0 + lane_j) * Isz + 4 * q];
            Wt[(4*q+0)*32 + lane_j] = w.x;
            Wt[(4*q+1)*32 + lane_j] = w.y;
            Wt[(4*q+2)*32 + lane_j] = w.z;
            Wt[(4*q+3)*32 + lane_j] = w.w;
        }
    }

    const int bg = tid & 7, hg = (tid >> 3) & 7, is = tid >> 6;  // I-split 4
    const int pb = tid & 15, php = tid >> 4;                     // phase-2 roles
    const int pod = bt * 2 + (pb >> 3), bi = pb & 7;
    const float pbias0 = b_ih[h0 + php*2 + 0] + b_hh[h0 + php*2 + 0];
    const float pbias1 = b_ih[h0 + php*2 + 1] + b_hh[h0 + php*2 + 1];

    for (int tt = 0; tt < TQ; tt++) {
        const int t = tq * TQ + tt;
        __syncthreads();   // xs2/red reuse; covers Wt on first iter
        // Stage x tile replicated: xs2[b][i] = {x,x}
        for (int j = 0; j < 4; j++) {
            int idx = tid + 256 * j;                 // 1024 float4 loads
            int r = idx >> 6, q = idx & 63;
            float4 x = *(const float4*)&inputs[((size_t)(b0 + r) * Tlen + t) * Isz + 4 * q];
            u64 p0, p1, p2, p3;
            PACK2(p0, x.x, x.x); PACK2(p1, x.y, x.y);
            PACK2(p2, x.z, x.z); PACK2(p3, x.w, x.w);
            u64* dst = &xs2[r * XSROW + 4 * q];
            dst[0] = p0; dst[1] = p1; dst[2] = p2; dst[3] = p3;
        }
        __syncthreads();

        u64 a00 = 0, a10 = 0, a01 = 0, a11 = 0;
        const u64* xr0 = &xs2[(2 * bg + 0) * XSROW + is * 64];
        const u64* xr1 = &xs2[(2 * bg + 1) * XSROW + is * 64];
        const u64* wr  = &Wtu[(is * 64) * 16 + hg * 2];
        #pragma unroll 8
        for (int ii = 0; ii < 64; ii++) {
            ulonglong2 w = *(const ulonglong2*)&wr[ii * 16];
            u64 x0 = xr0[ii];
            u64 x1 = xr1[ii];
            FMA2(a00, w.x, x0);
            FMA2(a10, w.y, x0);
            FMA2(a01, w.x, x1);
            FMA2(a11, w.y, x1);
        }
        u64* rb = &red[is * 256 + (hg * 2) * 16 + bg * 2];
        rb[0]  = a00;
        rb[16] = a10;
        rb[1]  = a01;
        rb[17] = a11;
        __syncthreads();

        // Phase 2: reduce I-splits, add bias, store xp
        u64 s, u;
        ADD2(s, red[0*256 + php*16 + pb], red[1*256 + php*16 + pb]);
        ADD2(u, red[2*256 + php*16 + pb], red[3*256 + php*16 + pb]);
        ADD2(s, s, u);
        float v0, v1; UNPACK2(v0, v1, s);
        float* dst = &g_xp[(((size_t)t * PODS + pod) * Hsz + h0 + php * 2) * PB + bi];
        dst[0]  = v0 + pbias0;
        dst[PB] = v1 + pbias1;
    }
}

// ---------------------------------------------------------------------------
// Persistent recurrence + fused init + fused readout.
// 128 blocks = 16 pods x 8 blocks; 512 threads (4 warps/SMSP).
// Block = 64 h-rows x 8 batches. K-split 8 in GEMM.
// smem: Wt[512][64] f32 (128KB) + hs2[512][8] u64 (32KB) + red[8][256] u64 (16KB)
// ---------------------------------------------------------------------------
__global__ void __launch_bounds__(512) rnn_kernel(
    const float* __restrict__ W_hh, const float* __restrict__ h0g,
    const float* __restrict__ W_out, const float* __restrict__ b_out,
    float* __restrict__ out)
{
    extern __shared__ float smem[];
    float* Wt  = smem;                              // [512][64]: Wt[k][j]=W_hh[h0+j][k]
    u64*   hs2 = (u64*)(smem + Hsz * 64);           // [512][8]: {h[k][b], h[k][b]}
    u64*   red = (u64*)(smem + Hsz * 64 + Hsz * PB * 2);  // [8][256]
    const u64* Wtu = (const u64*)Wt;
    float* hs2f = (float*)hs2;

    const int blk = blockIdx.x;
    const int pod = blk >> 3, ht = blk & 7;
    const int h0 = ht * 64;
    const int tid = threadIdx.x;

    // Stage this block's 64-row W_hh slice once (reused all 512 steps)
    {
        const int j = tid & 63, qg = tid >> 6;               // qg 0..7
        for (int q = qg; q < 128; q += 8) {
            float4 w = *(const float4*)&W_hh[(h0 + j) * Hsz + 4 * q];
            Wt[(4*q+0)*64 + j] = w.x;
            Wt[(4*q+1)*64 + j] = w.y;
            Wt[(4*q+2)*64 + j] = w.z;
            Wt[(4*q+3)*64 + j] = w.w;
        }
    }

    const int bg = tid & 3, hg = (tid >> 2) & 15, ks = tid >> 6;  // K-split 8
    const int pb = tid & 7, php = tid >> 3;                       // phase-2 (tid<256)
    const float invT = 1.0f / 512.0f;

    unsigned base_gen = 0;
    if (tid == 0) base_gen = *(volatile unsigned*)&g_pbar_gen[pod * 32];

    for (int t = 0; t < Tlen; t++) {
        __syncthreads();   // covers W staging on t=0; hs2/red reuse
        if (t == 0) {
            // Fused hinit: hs2[k][b] = {h0[k], h0[k]} for all b
            float v = h0g[tid];                      // tid == k (512 threads)
            u64 p; PACK2(p, v, v);
            u64* dst = &hs2[tid * PB];
            #pragma unroll
            for (int j2 = 0; j2 < PB; j2++) dst[j2] = p;
        } else {
            // Stage pod h slice (16KB) from L2, replicated into hs2
            const float4* hsrc = (const float4*)(g_h[t & 1] + pod * (Hsz * PB));
            for (int j2 = 0; j2 < 2; j2++) {
                int idx = tid + 512 * j2;                    // 1024 float4
                float4 v = __ldcg(hsrc + idx);
                u64 p0, p1, p2, p3;
                PACK2(p0, v.x, v.x); PACK2(p1, v.y, v.y);
                PACK2(p2, v.z, v.z); PACK2(p3, v.w, v.w);
                u64* dst = &hs2[idx * 4];
                dst[0] = p0; dst[1] = p1; dst[2] = p2; dst[3] = p3;
            }
        }
        // Prefetch xp for phase-2 threads (latency hidden by GEMM)
        float xp0 = 0.f, xp1 = 0.f;
        if (tid < 256) {
            const size_t xbase = (((size_t)t * PODS + pod) * Hsz + h0 + php * 2) * PB + pb;
            xp0 = __ldg(&g_xp[xbase]);
            xp1 = __ldg(&g_xp[xbase + PB]);
        }
        __syncthreads();

        // GEMM slice: thread tile 4h x 2b over 64 k; 4 FFMA2 per 2 LDS.128 per k
        u64 a00 = 0, a10 = 0, a01 = 0, a11 = 0;
        const u64* hr = &hs2[(ks * 64) * PB + bg * 2];
        const u64* wr = &Wtu[(ks * 64) * 32 + hg * 2];
        #pragma unroll 8
        for (int kk = 0; kk < 64; kk++) {
            ulonglong2 w  = *(const ulonglong2*)&wr[kk * 32];  // {W[h2hg..],W[h2hg+2..]}
            ulonglong2 hv = *(const ulonglong2*)&hr[kk * 8];   // {{b0,b0},{b1,b1}}
            FMA2(a00, w.x, hv.x);
            FMA2(a10, w.y, hv.x);
            FMA2(a01, w.x, hv.y);
            FMA2(a11, w.y, hv.y);
        }
        u64* rb = &red[ks * 256 + (2 * hg) * 8 + 2 * bg];
        rb[0] = a00;   // hpair 2hg,   b 2bg
        rb[8] = a10;   // hpair 2hg+1, b 2bg
        rb[1] = a01;
        rb[9] = a11;
        __syncthreads();

        // Phase 2: reduce 8 K-splits, epilogue h_new = h + tanh(acc+xp)*invT
        if (tid < 256) {
            u64 s0, s1, s2, s3;
            ADD2(s0, red[0*256 + php*8 + pb], red[1*256 + php*8 + pb]);
            ADD2(s1, red[2*256 + php*8 + pb], red[3*256 + php*8 + pb]);
            ADD2(s2, red[4*256 + php*8 + pb], red[5*256 + php*8 + pb]);
            ADD2(s3, red[6*256 + php*8 + pb], red[7*256 + php*8 + pb]);
            ADD2(s0, s0, s1);
            ADD2(s2, s2, s3);
            ADD2(s0, s0, s2);
            float v0, v1; UNPACK2(v0, v1, s0);
            float hp0 = hs2f[((h0 + php*2 + 0) * PB + pb) * 2];
            float hp1 = hs2f[((h0 + php*2 + 1) * PB + pb) * 2];
            float* hdst = g_h[(t + 1) & 1] + pod * (Hsz * PB) + (h0 + php * 2) * PB + pb;
            hdst[0]  = hp0 + tanhf(v0 + xp0) * invT;
            hdst[PB] = hp1 + tanhf(v1 + xp1) * invT;
        }

        // Pod-local barrier (8 blocks, monotonic generation counter)
        __syncthreads();
        if (tid == 0) {
            __threadfence();
            unsigned target = base_gen + (unsigned)(t + 1);
            if (atomicAdd(&g_pbar_count[pod * 32], 1u) == PODB - 1) {
                atomicExch(&g_pbar_count[pod * 32], 0u);
                __threadfence();
                atomicExch(&g_pbar_gen[pod * 32], target);
            } else {
                while ((*(volatile unsigned*)&g_pbar_gen[pod * 32]) - base_gen < (unsigned)(t + 1)) { }
            }
        }
        __syncthreads();
    }

    // ---- Fused readout: out[b][o] = sum_k h_last[k][b]*W_out[o][k] + b_out[o]
    // Block (pod, ht) computes o in [ht*32, ht*32+32) for its pod's 8 batches.
    const int o0 = ht * 32;
    float* hsf = (float*)hs2;                        // reuse as plain [512][8]
    {
        // Final h (T=512 even -> parity 0); pod-synced by the last barrier.
        const float4* hsrc = (const float4*)(g_h[0] + pod * (Hsz * PB));
        for (int j2 = 0; j2 < 2; j2++) {
            int idx = tid + 512 * j2;
            float4 v = __ldcg(hsrc + idx);
            *((float4*)hsf + idx) = v;
        }
        // W_out slice transposed into (freed) Wt region: Wo[k][32]
        const int lane_j = tid & 31, qg = tid >> 5;          // qg 0..15
        for (int q = qg; q < 128; q += 16) {
            float4 w = *(const float4*)&W_out[(o0 + lane_j) * Hsz + 4 * q];
            Wt[(4*q+0)*32 + lane_j] = w.x;
            Wt[(4*q+1)*32 + lane_j] = w.y;
            Wt[(4*q+2)*32 + lane_j] = w.z;
            Wt[(4*q+3)*32 + lane_j] = w.w;
        }
    }
    __syncthreads();
    if (tid < 256) {
        const int b_ = tid & 7, og = tid >> 3;       // og 0..31
        float acc = 0.f;
        #pragma unroll 8
        for (int k = 0; k < Hsz; k++) {
            acc += hsf[k * PB + b_] * Wt[k * 32 + og];
        }
        out[(pod * PB + b_) * Osz + o0 + og] = acc + b_out[o0 + og];
    }
}

// ---------------------------------------------------------------------------
extern "C" void kernel_launch(void* const* d_in, const int* in_sizes, int n_in,
                              void* d_out, int out_size)
{
    const float* inputs = (const float*)d_in[0];
    const float* W_ih   = (const float*)d_in[1];
    const float* b_ih   = (const float*)d_in[2];
    const float* W_hh   = (const float*)d_in[3];
    const float* b_hh   = (const float*)d_in[4];
    const float* W_out  = (const float*)d_in[5];
    const float* b_out  = (const float*)d_in[6];
    const float* h0     = (const float*)d_in[7];
    float* out = (float*)d_out;

    const int SMEM_XP  = 8192 * 4 + 2 * 16 * XSROW * 8 + 1024 * 8;        // 73856 B
    const int SMEM_RNN = Hsz * 64 * 4 + Hsz * PB * 8 + 2048 * 8;          // 180224 B
    cudaFuncSetAttribute(xp_kernel,  cudaFuncAttributeMaxDynamicSharedMemorySize, SMEM_XP);
    cudaFuncSetAttribute(rnn_kernel, cudaFuncAttributeMaxDynamicSharedMemorySize, SMEM_RNN);

    xp_kernel<<<dim3(Tlen / TQ, NBT, Hsz / 32), 256, SMEM_XP>>>(inputs, W_ih, b_ih, b_hh);
    rnn_kernel<<<PODS * PODB, 512, SMEM_RNN>>>(W_hh, h0, W_out, b_out, out);
}

// round 9
// speedup vs baseline: 1.1017x; 1.1017x over previous
#include <cuda_runtime.h>
#include <math.h>

// Problem dims (fixed)
#define Bsz   128
#define Tlen  512
#define Isz   256
#define Hsz   512
#define Osz   256

// Pod decomposition: 16 independent pods x 8 blocks; each pod owns 8 batches,
// each block owns 64 h-rows of W_hh (128KB fp32 in smem).
#define PODS  16
#define PODB  8      // blocks per pod
#define PB    8      // batches per pod
#define NBT   8      // xp batch tiles (of 16)

// Packed f32x2 helpers (xp kernel)
#define FMA2(acc, a, b) \
    asm("fma.rn.f32x2 %0, %1, %2, %0;" : "+l"(acc) : "l"(a), "l"(b))
#define ADD2(d, a, b) \
    asm("add.rn.f32x2 %0, %1, %2;" : "=l"(d) : "l"(a), "l"(b))
#define PACK2(d, lo, hi) \
    asm("mov.b64 %0, {%1, %2};" : "=l"(d) : "f"(lo), "f"(hi))
#define UNPACK2(lo, hi, v) \
    asm("mov.b64 {%0, %1}, %2;" : "=f"(lo), "=f"(hi) : "l"(v))

typedef unsigned long long u64;

// Scratch (device globals; no runtime allocation)
__device__ float    g_xp[(size_t)Tlen * PODS * Hsz * PB]; // [t][pod][h][8]
__device__ float    g_h[2][PODS * Hsz * PB];              // [parity][pod][k][8]
__device__ unsigned g_pbar_count[PODS * 32];              // 128B-padded per pod
__device__ unsigned g_pbar_gen[PODS * 32];

// ---------------------------------------------------------------------------
// x_proj: xp[t][pod][h][b] = sum_i inputs[b][t][i]*W_ih[h][i] + b_ih[h]+b_hh[h]
// ---------------------------------------------------------------------------
#define TQ  8
#define XSROW 257

__global__ void __launch_bounds__(256) xp_kernel(
    const float* __restrict__ inputs, const float* __restrict__ W_ih,
    const float* __restrict__ b_ih,   const float* __restrict__ b_hh)
{
    extern __shared__ float smem[];
    float* Wt  = smem;                              // [256][32]: Wt[i][j]=W_ih[h0+j][i]
    u64*   xs2 = (u64*)(smem + 8192);               // [16][257]: xs2[b][i]={x,x}
    u64*   red = (u64*)(smem + 8192 + 2 * 16 * XSROW);  // [4][16][16]
    const u64* Wtu = (const u64*)Wt;

    const int tq = blockIdx.x, bt = blockIdx.y, ht = blockIdx.z;
    const int h0 = ht * 32, b0 = bt * 16;
    const int tid = threadIdx.x;

    // Stage W_ih tile transposed (once)
    {
        const int lane_j = tid & 31, qb = tid >> 5;          // qb 0..7
        for (int r = 0; r < 8; r++) {
            int q = qb + 8 * r;                              // 0..63
            float4 w = *(const float4*)&W_ih[(h0 + lane_j) * Isz + 4 * q];
            Wt[(4*q+0)*32 + lane_j] = w.x;
            Wt[(4*q+1)*32 + lane_j] = w.y;
            Wt[(4*q+2)*32 + lane_j] = w.z;
            Wt[(4*q+3)*32 + lane_j] = w.w;
        }
    }

    const int bg = tid & 7, hg = (tid >> 3) & 7, is = tid >> 6;  // I-split 4
    const int pb = tid & 15, php = tid >> 4;                     // phase-2 roles
    const int pod = bt * 2 + (pb >> 3), bi = pb & 7;
    const float pbias0 = b_ih[h0 + php*2 + 0] + b_hh[h0 + php*2 + 0];
    const float pbias1 = b_ih[h0 + php*2 + 1] + b_hh[h0 + php*2 + 1];

    for (int tt = 0; tt < TQ; tt++) {
        const int t = tq * TQ + tt;
        __syncthreads();   // xs2/red reuse; covers Wt on first iter
        for (int j = 0; j < 4; j++) {
            int idx = tid + 256 * j;                 // 1024 float4 loads
            int r = idx >> 6, q = idx & 63;
            float4 x = *(const float4*)&inputs[((size_t)(b0 + r) * Tlen + t) * Isz + 4 * q];
            u64 p0, p1, p2, p3;
            PACK2(p0, x.x, x.x); PACK2(p1, x.y, x.y);
            PACK2(p2, x.z, x.z); PACK2(p3, x.w, x.w);
            u64* dst = &xs2[r * XSROW + 4 * q];
            dst[0] = p0; dst[1] = p1; dst[2] = p2; dst[3] = p3;
        }
        __syncthreads();

        u64 a00 = 0, a10 = 0, a01 = 0, a11 = 0;
        const u64* xr0 = &xs2[(2 * bg + 0) * XSROW + is * 64];
        const u64* xr1 = &xs2[(2 * bg + 1) * XSROW + is * 64];
        const u64* wr  = &Wtu[(is * 64) * 16 + hg * 2];
        #pragma unroll 8
        for (int ii = 0; ii < 64; ii++) {
            ulonglong2 w = *(const ulonglong2*)&wr[ii * 16];
            u64 x0 = xr0[ii];
            u64 x1 = xr1[ii];
            FMA2(a00, w.x, x0);
            FMA2(a10, w.y, x0);
            FMA2(a01, w.x, x1);
            FMA2(a11, w.y, x1);
        }
        u64* rb = &red[is * 256 + (hg * 2) * 16 + bg * 2];
        rb[0]  = a00;
        rb[16] = a10;
        rb[1]  = a01;
        rb[17] = a11;
        __syncthreads();

        u64 s, u;
        ADD2(s, red[0*256 + php*16 + pb], red[1*256 + php*16 + pb]);
        ADD2(u, red[2*256 + php*16 + pb], red[3*256 + php*16 + pb]);
        ADD2(s, s, u);
        float v0, v1; UNPACK2(v0, v1, s);
        float* dst = &g_xp[(((size_t)t * PODS + pod) * Hsz + h0 + php * 2) * PB + bi];
        dst[0]  = v0 + pbias0;
        dst[PB] = v1 + pbias1;
    }
}

// ---------------------------------------------------------------------------
// Persistent recurrence + fused init + fused readout.
// 128 blocks = 16 pods x 8; 512 threads. Thread tile 8h x 4b, K-split 32.
// smem: Wt[512][64] f32 (128KB) + hs[512][8] f32 (16KB) + red[32][64][8] (64KB)
// Crossbar budget/step: GEMM 3072 + red ~1000 + staging ~200 cyc.
// FFMA budget/step: 4096 cyc (rt2). fma-pipe-bound by design.
// ---------------------------------------------------------------------------
__global__ void __launch_bounds__(512) rnn_kernel(
    const float* __restrict__ W_hh, const float* __restrict__ h0g,
    const float* __restrict__ W_out, const float* __restrict__ b_out,
    float* __restrict__ out)
{
    extern __shared__ float smem[];
    float* Wt  = smem;                       // [512][64]: Wt[k][j]=W_hh[h0+j][k]
    float* hs  = smem + Hsz * 64;            // [512][8]:  hs[k][b] (plain)
    float* red = smem + Hsz * 64 + Hsz * PB; // [32][64][8] partials
    const float4* Wt4 = (const float4*)Wt;
    const float4* hs4 = (const float4*)hs;

    const int blk = blockIdx.x;
    const int pod = blk >> 3, ht = blk & 7;
    const int h0 = ht * 64;
    const int tid = threadIdx.x;

    // Stage this block's 64-row W_hh slice once (reused all 512 steps)
    {
        const int j = tid & 63, qg = tid >> 6;               // qg 0..7
        for (int q = qg; q < 128; q += 8) {
            float4 w = *(const float4*)&W_hh[(h0 + j) * Hsz + 4 * q];
            Wt[(4*q+0)*64 + j] = w.x;
            Wt[(4*q+1)*64 + j] = w.y;
            Wt[(4*q+2)*64 + j] = w.z;
            Wt[(4*q+3)*64 + j] = w.w;
        }
    }

    // GEMM roles: tid = ks*16 + hg*2 + bg
    const int ks = tid >> 4;          // 0..31, k range [ks*16, ks*16+16)
    const int hg = (tid >> 1) & 7;    // 8 h-rows: hg*8..
    const int bg = tid & 1;           // 4 batches: bg*4..
    // Phase-2/epilogue roles: tid -> (h = tid>>3, b = tid&7)
    const int ph = tid >> 3, pb = tid & 7;
    const float invT = 1.0f / 512.0f;

    unsigned base_gen = 0;
    if (tid == 0) base_gen = *(volatile unsigned*)&g_pbar_gen[pod * 32];

    for (int t = 0; t < Tlen; t++) {
        __syncthreads();   // hs/red reuse; covers Wt staging on t=0
        if (t == 0) {
            // Fused hinit: hs[k][b] = h0[k]
            float v = h0g[tid];                      // tid == k
            float4 p = make_float4(v, v, v, v);
            float4* dst = (float4*)&hs[tid * PB];
            dst[0] = p; dst[1] = p;
        } else {
            // Stage pod h slice (16KB) from L2
            const float4* hsrc = (const float4*)(g_h[t & 1] + pod * (Hsz * PB));
            for (int j2 = 0; j2 < 2; j2++) {
                int idx = tid + 512 * j2;                    // 1024 float4
                ((float4*)hs)[idx] = __ldcg(hsrc + idx);
            }
        }
        // Prefetch xp for this thread's epilogue output (hidden by GEMM)
        const float xp = __ldg(&g_xp[(((size_t)t * PODS + pod) * Hsz + h0) * PB + tid]);
        __syncthreads();

        // GEMM slice: acc[8h][4b], 3 LDS.128 + 32 FFMA per k (1.5 B/MAC)
        float acc[8][4];
        #pragma unroll
        for (int i = 0; i < 8; i++)
            #pragma unroll
            for (int j = 0; j < 4; j++) acc[i][j] = 0.f;

        const float4* wrow = &Wt4[(ks * 16) * 16 + hg * 2];
        const float4* hrow = &hs4[(ks * 16) * 2 + bg];
        #pragma unroll
        for (int kk = 0; kk < 16; kk++) {
            float4 w0 = wrow[kk * 16];
            float4 w1 = wrow[kk * 16 + 1];
            float4 hv = hrow[kk * 2];
            float wv[8] = {w0.x, w0.y, w0.z, w0.w, w1.x, w1.y, w1.z, w1.w};
            float hb[4] = {hv.x, hv.y, hv.z, hv.w};
            #pragma unroll
            for (int i = 0; i < 8; i++)
                #pragma unroll
                for (int j = 0; j < 4; j++)
                    acc[i][j] += wv[i] * hb[j];
        }
        // Store partials: red[ks][hg*8+i][bg*4..+3]
        {
            float* rb = &red[(ks * 64 + hg * 8) * PB + bg * 4];
            #pragma unroll
            for (int i = 0; i < 8; i++)
                *(float4*)&rb[i * PB] = *(float4*)&acc[i][0];
        }
        __syncthreads();

        // Phase 2: reduce 32 K-splits, epilogue h_new = h + tanh(acc+xp)*invT
        {
            float s0 = 0.f, s1 = 0.f, s2 = 0.f, s3 = 0.f;
            const float* rp = &red[tid];             // stride 512 floats over ks
            #pragma unroll
            for (int k2 = 0; k2 < 8; k2++) {
                s0 += rp[(4*k2+0) * 512];
                s1 += rp[(4*k2+1) * 512];
                s2 += rp[(4*k2+2) * 512];
                s3 += rp[(4*k2+3) * 512];
            }
            float v = (s0 + s1) + (s2 + s3);
            float hp = hs[(h0 + ph) * PB + pb];      // = hs[h0*8 + tid]
            float hnew = hp + tanhf(v + xp) * invT;
            g_h[(t + 1) & 1][pod * (Hsz * PB) + h0 * PB + tid] = hnew;
        }

        // Pod-local barrier (8 blocks, monotonic generation counter)
        __syncthreads();
        if (tid == 0) {
            __threadfence();
            unsigned target = base_gen + (unsigned)(t + 1);
            if (atomicAdd(&g_pbar_count[pod * 32], 1u) == PODB - 1) {
                atomicExch(&g_pbar_count[pod * 32], 0u);
                __threadfence();
                atomicExch(&g_pbar_gen[pod * 32], target);
            } else {
                while ((*(volatile unsigned*)&g_pbar_gen[pod * 32]) - base_gen < (unsigned)(t + 1)) { }
            }
        }
        __syncthreads();
    }

    // ---- Fused readout: out[b][o] = sum_k h_last[k][b]*W_out[o][k] + b_out[o]
    // Block (pod, ht) computes o in [ht*32, ht*32+32) for its pod's 8 batches.
    const int o0 = ht * 32;
    {
        // Final h (T=512 even -> parity 0); pod-synced by the last barrier.
        const float4* hsrc = (const float4*)(g_h[0] + pod * (Hsz * PB));
        for (int j2 = 0; j2 < 2; j2++) {
            int idx = tid + 512 * j2;
            ((float4*)hs)[idx] = __ldcg(hsrc + idx);
        }
        // W_out slice transposed into (freed) Wt region: Wo[k][32]
        const int lane_j = tid & 31, qg = tid >> 5;          // qg 0..15
        for (int q = qg; q < 128; q += 16) {
            float4 w = *(const float4*)&W_out[(o0 + lane_j) * Hsz + 4 * q];
            Wt[(4*q+0)*32 + lane_j] = w.x;
            Wt[(4*q+1)*32 + lane_j] = w.y;
            Wt[(4*q+2)*32 + lane_j] = w.z;
            Wt[(4*q+3)*32 + lane_j] = w.w;
        }
    }
    __syncthreads();
    if (tid < 256) {
        const int b_ = tid & 7, og = tid >> 3;       // og 0..31
        float acc = 0.f;
        #pragma unroll 8
        for (int k = 0; k < Hsz; k++) {
            acc += hs[k * PB + b_] * Wt[k * 32 + og];
        }
        out[(pod * PB + b_) * Osz + o0 + og] = acc + b_out[o0 + og];
    }
}

// ---------------------------------------------------------------------------
extern "C" void kernel_launch(void* const* d_in, const int* in_sizes, int n_in,
                              void* d_out, int out_size)
{
    const float* inputs = (const float*)d_in[0];
    const float* W_ih   = (const float*)d_in[1];
    const float* b_ih   = (const float*)d_in[2];
    const float* W_hh   = (const float*)d_in[3];
    const float* b_hh   = (const float*)d_in[4];
    const float* W_out  = (const float*)d_in[5];
    const float* b_out  = (const float*)d_in[6];
    const float* h0     = (const float*)d_in[7];
    float* out = (float*)d_out;

    const int SMEM_XP  = 8192 * 4 + 2 * 16 * XSROW * 8 + 1024 * 8;            // 73856 B
    const int SMEM_RNN = (Hsz * 64 + Hsz * PB + 32 * 64 * PB) * 4;            // 212992 B
    cudaFuncSetAttribute(xp_kernel,  cudaFuncAttributeMaxDynamicSharedMemorySize, SMEM_XP);
    cudaFuncSetAttribute(rnn_kernel, cudaFuncAttributeMaxDynamicSharedMemorySize, SMEM_RNN);

    xp_kernel<<<dim3(Tlen / TQ, NBT, Hsz / 32), 256, SMEM_XP>>>(inputs, W_ih, b_ih, b_hh);
    rnn_kernel<<<PODS * PODB, 512, SMEM_RNN>>>(W_hh, h0, W_out, b_out, out);
}